// round 2
// baseline (speedup 1.0000x reference)
#include <cuda_runtime.h>

typedef unsigned long long u64;
#define BATCH 131072

// inter-phase state: concat layout [b][96], enc at 0..63, cent at 64..95
__device__ float g_h0[(size_t)BATCH * 96];
__device__ float g_c0[(size_t)BATCH * 96];

__device__ __forceinline__ float ex2f(float x){ float y; asm("ex2.approx.f32 %0, %1;" : "=f"(y) : "f"(x)); return y; }
__device__ __forceinline__ float rcpf(float x){ float y; asm("rcp.approx.f32 %0, %1;" : "=f"(y) : "f"(x)); return y; }
__device__ __forceinline__ float sigmf(float x){ return rcpf(1.0f + ex2f(-1.4426950408889634f * x)); }
__device__ __forceinline__ float tanhf_(float x){ return 1.0f - 2.0f * rcpf(1.0f + ex2f(2.8853900817779268f * x)); }

// packed dual-fp32 FMA: d.lo += a.lo*b.lo ; d.hi += a.hi*b.hi
__device__ __forceinline__ void ffma2(u64 &d, u64 a, u64 b){
    asm("fma.rn.f32x2 %0, %1, %2, %0;" : "+l"(d) : "l"(a), "l"(b));
}
__device__ __forceinline__ float red2(u64 a){
    float lo, hi; asm("mov.b64 {%0, %1}, %2;" : "=f"(lo), "=f"(hi) : "l"(a)); return lo + hi;
}

// ---------------------------------------------------------------------------
// cent / enc phase. Thread = (element, unit-half s of S). h in SMEM per elem,
// c/h_new in registers. S<=2 and partner lanes adjacent => warp-local sync.
// ---------------------------------------------------------------------------
template<int H, int HP2, int T, int S, int NT, int OFF>
__global__ __launch_bounds__(NT)
void lstm_phase(const float* __restrict__ x_g,
                const float* __restrict__ Wih, const float* __restrict__ Whh,
                const float* __restrict__ bih, const float* __restrict__ bhh)
{
    constexpr int G = 4 * H;
    constexpr int NE = NT / S;
    constexpr int U = H / S;
    constexpr int TJ = 4;
    extern __shared__ float sm[];
    float* W  = sm;            // [G][H] row-major
    float* wx = W + G * H;     // [G][2]
    float* bs = wx + G * 2;    // [G]
    float* hs = bs + G;        // [NE][HP2]

    const int tid = threadIdx.x;
    for (int i = tid; i < G * H; i += NT) W[i]  = Whh[i];
    for (int i = tid; i < G * 2; i += NT) wx[i] = Wih[i];
    for (int i = tid; i < G;     i += NT) bs[i] = bih[i] + bhh[i];

    const int s = tid % S;
    const int e = tid / S;
    float* hrow = hs + e * HP2;
    for (int u = 0; u < U; u++) hrow[s * U + u] = 0.0f;
    __syncthreads();

    const size_t b = (size_t)blockIdx.x * NE + e;
    const float* xp = x_g + b * (size_t)(T * 2);

    float c[U], hn[U];
    #pragma unroll
    for (int u = 0; u < U; u++){ c[u] = 0.0f; hn[u] = 0.0f; }

    for (int t = 0; t < T; t++){
        const float2 xv = *(const float2*)(xp + 2 * t);
        #pragma unroll
        for (int tile = 0; tile < U / TJ; tile++){
            const int j0 = s * U + tile * TJ;
            u64 acc[4][TJ];
            #pragma unroll
            for (int r = 0; r < 4; r++)
                #pragma unroll
                for (int u = 0; u < TJ; u++) acc[r][u] = 0ULL;

            const u64* hp = (const u64*)hrow;
            #pragma unroll 2
            for (int k2 = 0; k2 < H / 2; k2++){
                u64 hv = hp[k2];
                #pragma unroll
                for (int r = 0; r < 4; r++)
                    #pragma unroll
                    for (int u = 0; u < TJ; u++){
                        u64 wv = *(const u64*)(W + (size_t)(j0 + u + H * r) * H + 2 * k2);
                        ffma2(acc[r][u], wv, hv);
                    }
            }
            #pragma unroll
            for (int u = 0; u < TJ; u++){
                const int j = j0 + u;
                float gi = red2(acc[0][u]) + bs[j]       + xv.x * wx[2*j]           + xv.y * wx[2*j+1];
                float gf = red2(acc[1][u]) + bs[H+j]     + xv.x * wx[2*(H+j)]       + xv.y * wx[2*(H+j)+1];
                float gg = red2(acc[2][u]) + bs[2*H+j]   + xv.x * wx[2*(2*H+j)]     + xv.y * wx[2*(2*H+j)+1];
                float go = red2(acc[3][u]) + bs[3*H+j]   + xv.x * wx[2*(3*H+j)]     + xv.y * wx[2*(3*H+j)+1];
                float cv = sigmf(gf) * c[tile*TJ+u] + sigmf(gi) * tanhf_(gg);
                c[tile*TJ+u]  = cv;
                hn[tile*TJ+u] = sigmf(go) * tanhf_(cv);
            }
        }
        __syncwarp();
        #pragma unroll
        for (int u = 0; u < U; u++) hrow[s * U + u] = hn[u];
        __syncwarp();
    }
    #pragma unroll
    for (int u = 0; u < U; u++){
        g_h0[b * 96 + OFF + s * U + u] = hn[u];
        g_c0[b * 96 + OFF + s * U + u] = c[u];
    }
}

// ---------------------------------------------------------------------------
// decoder: H=96, 30 steps, x == h  =>  combined W = Wih+Whh, bias = bih+bhh.
// S=2 (48 units per thread, partner lane adjacent). pos via shfl_xor fold.
// ---------------------------------------------------------------------------
#define DNT 256
__global__ __launch_bounds__(DNT)
void lstm_dec(const float* __restrict__ Wih, const float* __restrict__ Whh,
              const float* __restrict__ bih, const float* __restrict__ bhh,
              const float* __restrict__ Wemb, const float* __restrict__ bemb,
              float* __restrict__ out)
{
    constexpr int H = 96, G = 384, NE = DNT / 2, U = 48, TJ = 4, HP2 = 98;
    extern __shared__ float sm[];
    float* W  = sm;            // [384][96]
    float* bs = W + G * H;     // [384]
    float* we = bs + G;        // [192]
    float* hs = we + 192;      // [NE][98]

    const int tid = threadIdx.x;
    for (int i = tid; i < G * H; i += DNT) W[i]  = Wih[i] + Whh[i];
    for (int i = tid; i < G;     i += DNT) bs[i] = bih[i] + bhh[i];
    for (int i = tid; i < 192;   i += DNT) we[i] = Wemb[i];

    const int s = tid & 1;
    const int e = tid >> 1;
    float* hrow = hs + e * HP2;
    const size_t b = (size_t)blockIdx.x * NE + e;

    float c[U], hn[U];
    #pragma unroll
    for (int u = 0; u < U; u++){
        float hv = g_h0[b * 96 + s * U + u];
        c[u]  = g_c0[b * 96 + s * U + u];
        hn[u] = hv;
        hrow[s * U + u] = hv;
    }
    __syncthreads();

    const float bex = bemb[0], bey = bemb[1];
    float* op = out + b * 60;

    for (int t = 0; t < 30; t++){
        #pragma unroll
        for (int tile = 0; tile < U / TJ; tile++){
            const int j0 = s * U + tile * TJ;
            u64 acc[4][TJ];
            #pragma unroll
            for (int r = 0; r < 4; r++)
                #pragma unroll
                for (int u = 0; u < TJ; u++) acc[r][u] = 0ULL;

            const u64* hp = (const u64*)hrow;
            #pragma unroll 2
            for (int k2 = 0; k2 < H / 2; k2++){
                u64 hv = hp[k2];
                #pragma unroll
                for (int r = 0; r < 4; r++)
                    #pragma unroll
                    for (int u = 0; u < TJ; u++){
                        u64 wv = *(const u64*)(W + (size_t)(j0 + u + H * r) * H + 2 * k2);
                        ffma2(acc[r][u], wv, hv);
                    }
            }
            #pragma unroll
            for (int u = 0; u < TJ; u++){
                const int j = j0 + u;
                float gi = red2(acc[0][u]) + bs[j];
                float gf = red2(acc[1][u]) + bs[H+j];
                float gg = red2(acc[2][u]) + bs[2*H+j];
                float go = red2(acc[3][u]) + bs[3*H+j];
                float cv = sigmf(gf) * c[tile*TJ+u] + sigmf(gi) * tanhf_(gg);
                c[tile*TJ+u]  = cv;
                hn[tile*TJ+u] = sigmf(go) * tanhf_(cv);
            }
        }
        __syncwarp();
        #pragma unroll
        for (int u = 0; u < U; u++) hrow[s * U + u] = hn[u];
        __syncwarp();

        float px = 0.0f, py = 0.0f;
        #pragma unroll
        for (int u = 0; u < U; u++){
            px += hn[u] * we[s * U + u];
            py += hn[u] * we[96 + s * U + u];
        }
        px += __shfl_xor_sync(0xffffffffu, px, 1);
        py += __shfl_xor_sync(0xffffffffu, py, 1);
        if (s == 0){
            float2 o; o.x = px + bex; o.y = py + bey;
            *(float2*)(op + 2 * t) = o;
        }
    }
}

extern "C" void kernel_launch(void* const* d_in, const int* in_sizes, int n_in,
                              void* d_out, int out_size)
{
    (void)n_in; (void)out_size;
    const float* traj  = (const float*)d_in[0];
    const float* cent  = (const float*)d_in[1];
    const float* Wih_c = (const float*)d_in[2];
    const float* Whh_c = (const float*)d_in[3];
    const float* bih_c = (const float*)d_in[4];
    const float* bhh_c = (const float*)d_in[5];
    const float* Wih_e = (const float*)d_in[6];
    const float* Whh_e = (const float*)d_in[7];
    const float* bih_e = (const float*)d_in[8];
    const float* bhh_e = (const float*)d_in[9];
    const float* Wih_d = (const float*)d_in[10];
    const float* Whh_d = (const float*)d_in[11];
    const float* bih_d = (const float*)d_in[12];
    const float* bhh_d = (const float*)d_in[13];
    const float* W_emb = (const float*)d_in[14];
    const float* b_emb = (const float*)d_in[15];
    float* out = (float*)d_out;

    const int B = in_sizes[0] / 40;   // input_traj [B][20][2]

    // SMEM bytes
    const int smc = (128*32 + 128*2 + 128 + 256*34) * 4;               //  52,736
    const int sme = (256*64 + 256*2 + 256 + 128*66) * 4;               // 102,400
    const int smd = (384*96 + 384 + 192 + 128*98) * 4;                 // 199,936

    cudaFuncSetAttribute(lstm_phase<32,34,100,1,256,64>, cudaFuncAttributeMaxDynamicSharedMemorySize, smc);
    cudaFuncSetAttribute(lstm_phase<64,66, 20,2,256, 0>, cudaFuncAttributeMaxDynamicSharedMemorySize, sme);
    cudaFuncSetAttribute(lstm_dec, cudaFuncAttributeMaxDynamicSharedMemorySize, smd);

    // centerline LSTM (H=32, T=100) -> g_h0/g_c0[.., 64..95]
    lstm_phase<32,34,100,1,256,64><<<B/256, 256, smc>>>(cent, Wih_c, Whh_c, bih_c, bhh_c);
    // encoder LSTM (H=64, T=20)    -> g_h0/g_c0[.., 0..63]
    lstm_phase<64,66, 20,2,256, 0><<<B/128, 256, sme>>>(traj, Wih_e, Whh_e, bih_e, bhh_e);
    // decoder (H=96, 30 steps) -> out [B][30][2]
    lstm_dec<<<B/128, 256, smd>>>(Wih_d, Whh_d, bih_d, bhh_d, W_emb, b_emb, out);
}